// round 2
// baseline (speedup 1.0000x reference)
#include <cuda_runtime.h>
#include <cstdint>

// Problem dims (fixed by the dataset)
#define N_NODES 50000
#define N_EDGES 800000
#define E_TOT   850000   // + self loops
#define IN0     20
#define HID     64
#define OUTC    128
#define TB      256

// ---------------- scratch (device globals; no allocation allowed) ----------
__device__ __align__(16) float    g_feat0[N_NODES * IN0];      //  4.0 MB
__device__ __align__(16) float    g_h[N_NODES * 256];          // 51.2 MB
__device__ __align__(16) float    g_sA[N_NODES * 4];           //  0.8 MB
__device__ __align__(16) float    g_sB[N_NODES * 4];           //  0.8 MB
__device__ __align__(16) float    g_r[E_TOT * 4];              // 13.6 MB (scores, then exp-values)
__device__ __align__(16) float    g_accum[N_NODES * HID];      // 12.8 MB
__device__ float    g_Z[4];
__device__ unsigned g_maxbits[4];
__device__ float    g_invZ[4];

// orderable-uint encoding of float for atomicMax
__device__ __forceinline__ unsigned encf(float f) {
    unsigned u = __float_as_uint(f);
    return (u & 0x80000000u) ? ~u : (u | 0x80000000u);
}
__device__ __forceinline__ float decf(unsigned v) {
    return (v & 0x80000000u) ? __uint_as_float(v ^ 0x80000000u) : __uint_as_float(~v);
}
#define ENC_NEG_INF 0x007FFFFFu   // encf(-inf)
#define NEG_INF_F   __int_as_float(0xff800000)

// ---------------- feature build: concat(x, emb[joint_types]) ---------------
__global__ void feat0_kernel(const float* __restrict__ x,
                             const int*   __restrict__ jt,
                             const float* __restrict__ emb) {
    int i = blockIdx.x * blockDim.x + threadIdx.x;
    if (i >= N_NODES * IN0) return;
    int n = i / IN0, k = i - n * IN0;
    float v;
    if (k < 4) v = x[n * 4 + k];
    else       v = __ldg(&emb[jt[n] * 16 + (k - 4)]);
    g_feat0[i] = v;
}

// ---------------- GEMM: out[N, OUT] = act(feat[N, IN]) @ W[OUT, IN]^T ------
// blockDim must equal OUT. Each thread owns one output column (W row in regs),
// block processes 8 consecutive node rows via smem-staged features.
// ELU (optional) is applied to the features as they are staged into smem,
// fusing the previous layer's activation into this load.
template<int IN, int OUT, bool ELU>
__global__ void gemm_kernel(const float* __restrict__ feat,
                            const float* __restrict__ W,
                            float* __restrict__ out) {
    constexpr int ROWS = 8;
    __shared__ __align__(16) float sfeat[ROWS * IN];
    int row0 = blockIdx.x * ROWS;
    for (int i = threadIdx.x; i < ROWS * IN; i += OUT) {
        float v = feat[row0 * IN + i];
        if (ELU) v = v > 0.f ? v : expm1f(v);
        sfeat[i] = v;
    }
    float wreg[IN];
#pragma unroll
    for (int k = 0; k < IN; k++) wreg[k] = __ldg(&W[threadIdx.x * IN + k]);
    __syncthreads();
#pragma unroll
    for (int r = 0; r < ROWS; r++) {
        const float4* sf4 = (const float4*)(sfeat + r * IN);
        float acc = 0.f;
#pragma unroll
        for (int k4 = 0; k4 < IN / 4; k4++) {
            float4 f = sf4[k4];
            acc += wreg[4 * k4 + 0] * f.x;
            acc += wreg[4 * k4 + 1] * f.y;
            acc += wreg[4 * k4 + 2] * f.z;
            acc += wreg[4 * k4 + 3] * f.w;
        }
        out[(size_t)(row0 + r) * OUT + threadIdx.x] = acc;
    }
}

// ---------------- per-node attention scores s = h . a ----------------------
__global__ void s_kernel4(const float* __restrict__ h,
                          const float* __restrict__ asrc,
                          const float* __restrict__ adst) {
    int gw   = (blockIdx.x * blockDim.x + threadIdx.x) >> 5;
    int lane = threadIdx.x & 31;
    if (gw >= N_NODES) return;
    const float* hr = h + (size_t)gw * 256;
#pragma unroll
    for (int hh = 0; hh < 4; hh++) {
        float v0 = hr[hh * 64 + lane], v1 = hr[hh * 64 + 32 + lane];
        float a = v0 * __ldg(&asrc[hh * 64 + lane]) + v1 * __ldg(&asrc[hh * 64 + 32 + lane]);
        float b = v0 * __ldg(&adst[hh * 64 + lane]) + v1 * __ldg(&adst[hh * 64 + 32 + lane]);
#pragma unroll
        for (int off = 16; off; off >>= 1) {
            a += __shfl_xor_sync(0xffffffffu, a, off);
            b += __shfl_xor_sync(0xffffffffu, b, off);
        }
        if (lane == 0) { g_sA[gw * 4 + hh] = a; g_sB[gw * 4 + hh] = b; }
    }
}

__global__ void s_kernel1(const float* __restrict__ h,
                          const float* __restrict__ asrc,
                          const float* __restrict__ adst) {
    int gw   = (blockIdx.x * blockDim.x + threadIdx.x) >> 5;
    int lane = threadIdx.x & 31;
    if (gw >= N_NODES) return;
    const float* hr = h + (size_t)gw * 128;
    float a = 0.f, b = 0.f;
#pragma unroll
    for (int i = 0; i < 4; i++) {
        float v = hr[i * 32 + lane];
        a += v * __ldg(&asrc[i * 32 + lane]);
        b += v * __ldg(&adst[i * 32 + lane]);
    }
#pragma unroll
    for (int off = 16; off; off >>= 1) {
        a += __shfl_xor_sync(0xffffffffu, a, off);
        b += __shfl_xor_sync(0xffffffffu, b, off);
    }
    if (lane == 0) { g_sA[gw] = a; g_sB[gw] = b; }
}

// ---------------- softmax bookkeeping --------------------------------------
__global__ void reset_kernel() {
    int t = threadIdx.x;
    if (t < 4) { g_Z[t] = 0.f; g_maxbits[t] = ENC_NEG_INF; }
}

__global__ void invz_kernel(float invH) {
    int t = threadIdx.x;
    if (t < 4) g_invZ[t] = invH / g_Z[t];
}

// ---------------- edge scores + global max (H = 4) -------------------------
__global__ void score4_kernel(const int* __restrict__ ei,
                              const float* __restrict__ eattr,
                              const float* __restrict__ We) {
    __shared__ float    sWe[16];
    __shared__ unsigned smax[4];
    if (threadIdx.x < 16) sWe[threadIdx.x] = We[threadIdx.x];
    if (threadIdx.x < 4)  smax[threadIdx.x] = ENC_NEG_INF;
    __syncthreads();
    float m0 = NEG_INF_F, m1 = NEG_INF_F, m2 = NEG_INF_F, m3 = NEG_INF_F;
    int stride = gridDim.x * blockDim.x;
    for (int e = blockIdx.x * blockDim.x + threadIdx.x; e < E_TOT; e += stride) {
        int s, d; float4 ea;
        if (e < N_EDGES) {
            s = __ldg(&ei[e]); d = __ldg(&ei[N_EDGES + e]);
            ea = __ldg((const float4*)eattr + e);
        } else {
            s = d = e - N_EDGES; ea = make_float4(0.f, 0.f, 0.f, 0.f);
        }
        float4 va = __ldg((const float4*)g_sA + d);
        float4 vb = __ldg((const float4*)g_sB + s);
        float r0 = va.x + vb.x + ea.x * sWe[0]  + ea.y * sWe[1]  + ea.z * sWe[2]  + ea.w * sWe[3];
        float r1 = va.y + vb.y + ea.x * sWe[4]  + ea.y * sWe[5]  + ea.z * sWe[6]  + ea.w * sWe[7];
        float r2 = va.z + vb.z + ea.x * sWe[8]  + ea.y * sWe[9]  + ea.z * sWe[10] + ea.w * sWe[11];
        float r3 = va.w + vb.w + ea.x * sWe[12] + ea.y * sWe[13] + ea.z * sWe[14] + ea.w * sWe[15];
        r0 = r0 > 0.f ? r0 : 0.2f * r0;
        r1 = r1 > 0.f ? r1 : 0.2f * r1;
        r2 = r2 > 0.f ? r2 : 0.2f * r2;
        r3 = r3 > 0.f ? r3 : 0.2f * r3;
        ((float4*)g_r)[e] = make_float4(r0, r1, r2, r3);
        m0 = fmaxf(m0, r0); m1 = fmaxf(m1, r1); m2 = fmaxf(m2, r2); m3 = fmaxf(m3, r3);
    }
#pragma unroll
    for (int off = 16; off; off >>= 1) {
        m0 = fmaxf(m0, __shfl_xor_sync(0xffffffffu, m0, off));
        m1 = fmaxf(m1, __shfl_xor_sync(0xffffffffu, m1, off));
        m2 = fmaxf(m2, __shfl_xor_sync(0xffffffffu, m2, off));
        m3 = fmaxf(m3, __shfl_xor_sync(0xffffffffu, m3, off));
    }
    if ((threadIdx.x & 31) == 0) {
        atomicMax(&smax[0], encf(m0)); atomicMax(&smax[1], encf(m1));
        atomicMax(&smax[2], encf(m2)); atomicMax(&smax[3], encf(m3));
    }
    __syncthreads();
    if (threadIdx.x < 4) atomicMax(&g_maxbits[threadIdx.x], smax[threadIdx.x]);
}

__global__ void score1_kernel(const int* __restrict__ ei,
                              const float* __restrict__ eattr,
                              const float* __restrict__ We) {
    __shared__ float    sWe[4];
    __shared__ unsigned smax;
    if (threadIdx.x < 4)  sWe[threadIdx.x] = We[threadIdx.x];
    if (threadIdx.x == 0) smax = ENC_NEG_INF;
    __syncthreads();
    float m = NEG_INF_F;
    int stride = gridDim.x * blockDim.x;
    for (int e = blockIdx.x * blockDim.x + threadIdx.x; e < E_TOT; e += stride) {
        int s, d; float4 ea;
        if (e < N_EDGES) {
            s = __ldg(&ei[e]); d = __ldg(&ei[N_EDGES + e]);
            ea = __ldg((const float4*)eattr + e);
        } else {
            s = d = e - N_EDGES; ea = make_float4(0.f, 0.f, 0.f, 0.f);
        }
        float r = __ldg(&g_sA[d]) + __ldg(&g_sB[s])
                + ea.x * sWe[0] + ea.y * sWe[1] + ea.z * sWe[2] + ea.w * sWe[3];
        r = r > 0.f ? r : 0.2f * r;
        g_r[e] = r;
        m = fmaxf(m, r);
    }
#pragma unroll
    for (int off = 16; off; off >>= 1)
        m = fmaxf(m, __shfl_xor_sync(0xffffffffu, m, off));
    if ((threadIdx.x & 31) == 0) atomicMax(&smax, encf(m));
    __syncthreads();
    if (threadIdx.x == 0) atomicMax(&g_maxbits[0], smax);
}

// ---------------- exp + sum (stores exp-values back into g_r) --------------
__global__ void sumexp4_kernel() {
    __shared__ float ssum[4];
    if (threadIdx.x < 4) ssum[threadIdx.x] = 0.f;
    __syncthreads();
    float mf0 = decf(g_maxbits[0]), mf1 = decf(g_maxbits[1]);
    float mf2 = decf(g_maxbits[2]), mf3 = decf(g_maxbits[3]);
    float z0 = 0.f, z1 = 0.f, z2 = 0.f, z3 = 0.f;
    int stride = gridDim.x * blockDim.x;
    for (int e = blockIdx.x * blockDim.x + threadIdx.x; e < E_TOT; e += stride) {
        float4 r = ((const float4*)g_r)[e];
        float e0 = expf(r.x - mf0), e1 = expf(r.y - mf1);
        float e2 = expf(r.z - mf2), e3 = expf(r.w - mf3);
        ((float4*)g_r)[e] = make_float4(e0, e1, e2, e3);
        z0 += e0; z1 += e1; z2 += e2; z3 += e3;
    }
#pragma unroll
    for (int off = 16; off; off >>= 1) {
        z0 += __shfl_xor_sync(0xffffffffu, z0, off);
        z1 += __shfl_xor_sync(0xffffffffu, z1, off);
        z2 += __shfl_xor_sync(0xffffffffu, z2, off);
        z3 += __shfl_xor_sync(0xffffffffu, z3, off);
    }
    if ((threadIdx.x & 31) == 0) {
        atomicAdd(&ssum[0], z0); atomicAdd(&ssum[1], z1);
        atomicAdd(&ssum[2], z2); atomicAdd(&ssum[3], z3);
    }
    __syncthreads();
    if (threadIdx.x < 4) atomicAdd(&g_Z[threadIdx.x], ssum[threadIdx.x]);
}

__global__ void sumexp1_kernel() {
    __shared__ float ssum;
    if (threadIdx.x == 0) ssum = 0.f;
    __syncthreads();
    float mf = decf(g_maxbits[0]);
    float z = 0.f;
    int stride = gridDim.x * blockDim.x;
    for (int e = blockIdx.x * blockDim.x + threadIdx.x; e < E_TOT; e += stride) {
        float ev = expf(g_r[e] - mf);
        g_r[e] = ev;
        z += ev;
    }
#pragma unroll
    for (int off = 16; off; off >>= 1)
        z += __shfl_xor_sync(0xffffffffu, z, off);
    if ((threadIdx.x & 31) == 0) atomicAdd(&ssum, z);
    __syncthreads();
    if (threadIdx.x == 0) atomicAdd(&g_Z[0], ssum);
}

// ---------------- zero fill ------------------------------------------------
__global__ void zero_kernel(float4* __restrict__ p, int n4) {
    int i = blockIdx.x * blockDim.x + threadIdx.x;
    if (i < n4) p[i] = make_float4(0.f, 0.f, 0.f, 0.f);
}

// ---------------- edge message pass (H=4, C=64): head-mean folded ----------
// warp per edge; lane handles 2 output cols; red.add.v2.f32 into accum[N,64]
__global__ void edgepass4_kernel(const int* __restrict__ ei,
                                 const float* __restrict__ hbuf,
                                 float* __restrict__ accum) {
    int gw   = (blockIdx.x * blockDim.x + threadIdx.x) >> 5;
    int lane = threadIdx.x & 31;
    if (gw >= E_TOT) return;
    int e = gw, s, d;
    if (e < N_EDGES) { s = __ldg(&ei[e]); d = __ldg(&ei[N_EDGES + e]); }
    else             { s = d = e - N_EDGES; }
    float4 rv = __ldg((const float4*)g_r + e);
    float4 iz = *((const float4*)g_invZ);
    float a0 = rv.x * iz.x, a1 = rv.y * iz.y, a2 = rv.z * iz.z, a3 = rv.w * iz.w;
    const float2* hp = (const float2*)(hbuf + (size_t)s * 256);
    float2 v0 = __ldg(hp + lane);
    float2 v1 = __ldg(hp + 32 + lane);
    float2 v2 = __ldg(hp + 64 + lane);
    float2 v3 = __ldg(hp + 96 + lane);
    float ax = a0 * v0.x + a1 * v1.x + a2 * v2.x + a3 * v3.x;
    float ay = a0 * v0.y + a1 * v1.y + a2 * v2.y + a3 * v3.y;
    float* dp = accum + (size_t)d * 64 + lane * 2;
    asm volatile("red.global.add.v2.f32 [%0], {%1, %2};"
                 :: "l"(dp), "f"(ax), "f"(ay) : "memory");
}

// ---------------- edge message pass (H=1, C=128) → d_out -------------------
__global__ void edgepass1_kernel(const int* __restrict__ ei,
                                 const float* __restrict__ hbuf,
                                 float* __restrict__ out) {
    int gw   = (blockIdx.x * blockDim.x + threadIdx.x) >> 5;
    int lane = threadIdx.x & 31;
    if (gw >= E_TOT) return;
    int e = gw, s, d;
    if (e < N_EDGES) { s = __ldg(&ei[e]); d = __ldg(&ei[N_EDGES + e]); }
    else             { s = d = e - N_EDGES; }
    float a = __ldg(&g_r[e]) * g_invZ[0];
    const float4* hp = (const float4*)(hbuf + (size_t)s * 128);
    float4 v = __ldg(hp + lane);
    float* dp = out + (size_t)d * 128 + lane * 4;
    asm volatile("red.global.add.v4.f32 [%0], {%1, %2, %3, %4};"
                 :: "l"(dp), "f"(a * v.x), "f"(a * v.y), "f"(a * v.z), "f"(a * v.w)
                 : "memory");
}

// ---------------- host -----------------------------------------------------
extern "C" void kernel_launch(void* const* d_in, const int* in_sizes, int n_in,
                              void* d_out, int out_size) {
    (void)in_sizes; (void)n_in; (void)out_size;
    const float* x     = (const float*)d_in[0];
    const int*   ei    = (const int*)  d_in[1];
    const float* eattr = (const float*)d_in[2];
    const int*   jt    = (const int*)  d_in[3];
    const float* emb   = (const float*)d_in[4];
    const float* W0    = (const float*)d_in[5];
    const float* as0   = (const float*)d_in[6];
    const float* ad0   = (const float*)d_in[7];
    const float* We0   = (const float*)d_in[8];
    const float* W1    = (const float*)d_in[9];
    const float* as1   = (const float*)d_in[10];
    const float* ad1   = (const float*)d_in[11];
    const float* We1   = (const float*)d_in[12];
    const float* W2    = (const float*)d_in[13];
    const float* as2   = (const float*)d_in[14];
    const float* ad2   = (const float*)d_in[15];
    const float* We2   = (const float*)d_in[16];
    float* out = (float*)d_out;

    float *p_feat0, *p_h, *p_accum;
    cudaGetSymbolAddress((void**)&p_feat0, g_feat0);
    cudaGetSymbolAddress((void**)&p_h,     g_h);
    cudaGetSymbolAddress((void**)&p_accum, g_accum);

    const int EP_BLOCKS = (E_TOT * 32 + TB - 1) / TB;   // warp per edge
    const int SW_BLOCKS = 2048;                          // grid-stride softmax passes
    const int NW_BLOCKS = (N_NODES * 32 + TB - 1) / TB;  // warp per node

    feat0_kernel<<<(N_NODES * IN0 + TB - 1) / TB, TB>>>(x, jt, emb);

    // ---- layer 0 (H=4, C=64, IN=20) ----
    gemm_kernel<IN0, 256, false><<<N_NODES / 8, 256>>>(p_feat0, W0, p_h);
    s_kernel4<<<NW_BLOCKS, TB>>>(p_h, as0, ad0);
    reset_kernel<<<1, 32>>>();
    score4_kernel<<<SW_BLOCKS, TB>>>(ei, eattr, We0);
    sumexp4_kernel<<<SW_BLOCKS, TB>>>();
    invz_kernel<<<1, 32>>>(0.25f);
    zero_kernel<<<(N_NODES * HID / 4 + TB - 1) / TB, TB>>>((float4*)p_accum, N_NODES * HID / 4);
    edgepass4_kernel<<<EP_BLOCKS, TB>>>(ei, p_h, p_accum);

    // ---- layer 1 (H=4, C=64, IN=64); ELU fused into gemm feature load ----
    gemm_kernel<HID, 256, true><<<N_NODES / 8, 256>>>(p_accum, W1, p_h);
    s_kernel4<<<NW_BLOCKS, TB>>>(p_h, as1, ad1);
    reset_kernel<<<1, 32>>>();
    score4_kernel<<<SW_BLOCKS, TB>>>(ei, eattr, We1);
    sumexp4_kernel<<<SW_BLOCKS, TB>>>();
    invz_kernel<<<1, 32>>>(0.25f);
    zero_kernel<<<(N_NODES * HID / 4 + TB - 1) / TB, TB>>>((float4*)p_accum, N_NODES * HID / 4);
    edgepass4_kernel<<<EP_BLOCKS, TB>>>(ei, p_h, p_accum);

    // ---- layer 2 (H=1, C=128, IN=64); ELU fused; output -> d_out ----
    gemm_kernel<HID, OUTC, true><<<N_NODES / 8, OUTC>>>(p_accum, W2, p_h);
    s_kernel1<<<NW_BLOCKS, TB>>>(p_h, as2, ad2);
    reset_kernel<<<1, 32>>>();
    score1_kernel<<<SW_BLOCKS, TB>>>(ei, eattr, We2);
    sumexp1_kernel<<<SW_BLOCKS, TB>>>();
    invz_kernel<<<1, 32>>>(1.0f);
    zero_kernel<<<(N_NODES * OUTC / 4 + TB - 1) / TB, TB>>>((float4*)out, N_NODES * OUTC / 4);
    edgepass1_kernel<<<EP_BLOCKS, TB>>>(ei, p_h, out);
}